// round 12
// baseline (speedup 1.0000x reference)
#include <cuda_runtime.h>

// MovingAvgNorm: x (B=32, T=16384, D=80) fp32, window K=100 over T,
// reflect pad (50 left, 49 right), unbiased std.
//
// R12: champion structure (TSUB=256, NTH=320, group sums + exclusive
// prefix-scan init, 48-reg / 4-blocks-per-SM regime, L1 carveout hint,
// remainder-LDG-before-LDS overlap) + BALANCED phase 1: each warp gets
// exactly 84 of the 840 gsum entries (previously warps 0-5 did 96 while
// 7-9 did 64, and the barrier charged everyone for the skew).

#define MAN_B      32
#define MAN_T      16384
#define MAN_DV     20          // 80 floats = 20 float4
#define MAN_K      100
#define MAN_H      50
#define MAN_TSUB   256
#define MAN_NTH    320
#define MAN_SEG    16
#define MAN_NCHUNK (MAN_T / MAN_TSUB)     // 64
#define MAN_G      8
#define MAN_NGRP   42                      // groups cover local rows 0..335
#define MAN_GPRE   (MAN_NGRP + 1)          // 43 (exclusive prefix, +total)
#define MAN_GARR   (MAN_GPRE * MAN_DV)     // 860 float4 per array
#define MAN_SMEM   (2 * MAN_GARR * 16)     // 27520 B
#define MAN_ENT    (MAN_NGRP * MAN_DV)     // 840 gsum entries
#define MAN_EPW    84                      // entries per warp (840 / 10 warps)

__device__ __forceinline__ int refl(int o) {
    if (o < 0) return -o;
    if (o >= MAN_T) return 2 * MAN_T - 2 - o;
    return o;
}

__device__ __forceinline__ void acc(float4& s1, float4& s2, float4 v) {
    s1.x += v.x; s1.y += v.y; s1.z += v.z; s1.w += v.w;
    s2.x = fmaf(v.x, v.x, s2.x);
    s2.y = fmaf(v.y, v.y, s2.y);
    s2.z = fmaf(v.z, v.z, s2.z);
    s2.w = fmaf(v.w, v.w, s2.w);
}

__device__ __forceinline__ float norm1(float xc, float s1, float s2,
                                       float inv_k, float inv_k1) {
    float m   = s1 * inv_k;
    float var = (s2 - s1 * m) * inv_k1;
    float rsd = rsqrtf(fmaxf(var, 1e-24f));
    return (xc - m) * rsd;
}

__device__ __forceinline__ void step(float4& s1, float4& s2,
                                     float4 va, float4 vr) {
    s1.x += va.x - vr.x;  s1.y += va.y - vr.y;
    s1.z += va.z - vr.z;  s1.w += va.w - vr.w;
    s2.x = fmaf(va.x, va.x, fmaf(-vr.x, vr.x, s2.x));
    s2.y = fmaf(va.y, va.y, fmaf(-vr.y, vr.y, s2.y));
    s2.z = fmaf(va.z, va.z, fmaf(-vr.z, vr.z, s2.z));
    s2.w = fmaf(va.w, va.w, fmaf(-vr.w, vr.w, s2.w));
}

__global__ __launch_bounds__(MAN_NTH, 4) void moving_avg_norm_v12(
    const float4* __restrict__ x, float4* __restrict__ out)
{
    extern __shared__ float4 smem[];
    float4* g1 = smem;              // [43*20] group sums -> exclusive prefix
    float4* g2 = smem + MAN_GARR;   // [43*20]

    const int b  = blockIdx.x / MAN_NCHUNK;
    const int c  = blockIdx.x % MAN_NCHUNK;
    const int t0 = c * MAN_TSUB;

    const float4* __restrict__ xb = x + (size_t)b * MAN_T * MAN_DV;
    const bool edge = (c == 0) || (c == MAN_NCHUNK - 1);

    // ---- phase 1: 8-row group sums, groups 0..41 (local row L = t0-50+L)
    //      BALANCED: warp w handles entries [84w, 84w+84) ----
    {
        const int wid  = threadIdx.x >> 5;
        const int lane = threadIdx.x & 31;
        const int base = wid * MAN_EPW;
        const int end  = base + MAN_EPW;

        if (!edge) {
            #pragma unroll 3
            for (int idx = base + lane; idx < end; idx += 32) {
                const int g   = idx / MAN_DV;
                const int dvv = idx % MAN_DV;
                const float4* rp = xb + (t0 - MAN_H + g * MAN_G) * MAN_DV + dvv;
                float4 v0 = __ldg(rp + 0 * MAN_DV);
                float4 v1 = __ldg(rp + 1 * MAN_DV);
                float4 v2 = __ldg(rp + 2 * MAN_DV);
                float4 v3 = __ldg(rp + 3 * MAN_DV);
                float4 v4 = __ldg(rp + 4 * MAN_DV);
                float4 v5 = __ldg(rp + 5 * MAN_DV);
                float4 v6 = __ldg(rp + 6 * MAN_DV);
                float4 v7 = __ldg(rp + 7 * MAN_DV);
                float4 p1 = make_float4(0.f, 0.f, 0.f, 0.f);
                float4 p2 = make_float4(0.f, 0.f, 0.f, 0.f);
                acc(p1, p2, v0); acc(p1, p2, v1);
                acc(p1, p2, v2); acc(p1, p2, v3);
                acc(p1, p2, v4); acc(p1, p2, v5);
                acc(p1, p2, v6); acc(p1, p2, v7);
                g1[idx] = p1;
                g2[idx] = p2;
            }
        } else {
            #pragma unroll 1
            for (int idx = base + lane; idx < end; idx += 32) {
                const int g   = idx / MAN_DV;
                const int dvv = idx % MAN_DV;
                const int r0  = t0 - MAN_H + g * MAN_G;
                float4 p1 = make_float4(0.f, 0.f, 0.f, 0.f);
                float4 p2 = make_float4(0.f, 0.f, 0.f, 0.f);
                #pragma unroll 1
                for (int i = 0; i < MAN_G; ++i)
                    acc(p1, p2, __ldg(xb + refl(r0 + i) * MAN_DV + dvv));
                g1[idx] = p1;
                g2[idx] = p2;
            }
        }
    }
    __syncthreads();

    // ---- phase 2: in-place exclusive prefix scan over groups (40 lanes) ----
    if (threadIdx.x < 2 * MAN_DV) {
        float4* A = (threadIdx.x < MAN_DV) ? g1 : g2;
        const int dvv = threadIdx.x % MAN_DV;
        float4 run = make_float4(0.f, 0.f, 0.f, 0.f);
        #pragma unroll 6
        for (int g = 0; g < MAN_NGRP; ++g) {
            float4 tmp = A[g * MAN_DV + dvv];
            A[g * MAN_DV + dvv] = run;
            run.x += tmp.x; run.y += tmp.y; run.z += tmp.z; run.w += tmp.w;
        }
        A[MAN_NGRP * MAN_DV + dvv] = run;
    }
    __syncthreads();

    // ---- phase 3: 20 dv-lanes x 16 segments of 16 outputs ----
    const int dv  = threadIdx.x % MAN_DV;
    const int seg = threadIdx.x / MAN_DV;      // 0..15
    const int ts  = seg * MAN_SEG;             // local output row start

    const float inv_k  = 1.0f / MAN_K;
    const float inv_k1 = 1.0f / (MAN_K - 1);

    float4* __restrict__ ob = out + ((size_t)b * MAN_T + t0 + ts) * MAN_DV + dv;

    if (!edge) {
        const float4* rp = xb + (t0 + ts) * MAN_DV + dv;

        // issue remainder LDGs first (global latency), then LDS prefix diff
        float4 q0 = __ldg(rp + 46 * MAN_DV);
        float4 q1 = __ldg(rp + 47 * MAN_DV);
        float4 q2 = __ldg(rp + 48 * MAN_DV);
        float4 q3 = __ldg(rp + 49 * MAN_DV);

        // window [ts, ts+100) = groups 2s..2s+11 (96 rows) + rows ts+96..99
        float4 lo1 = g1[(2 * seg) * MAN_DV + dv];
        float4 hi1 = g1[(2 * seg + 12) * MAN_DV + dv];
        float4 lo2 = g2[(2 * seg) * MAN_DV + dv];
        float4 hi2 = g2[(2 * seg + 12) * MAN_DV + dv];
        float4 s1 = make_float4(hi1.x - lo1.x, hi1.y - lo1.y,
                                hi1.z - lo1.z, hi1.w - lo1.w);
        float4 s2 = make_float4(hi2.x - lo2.x, hi2.y - lo2.y,
                                hi2.z - lo2.z, hi2.w - lo2.w);
        acc(s1, s2, q0); acc(s1, s2, q1); acc(s1, s2, q2); acc(s1, s2, q3);

        #pragma unroll 8
        for (int j = 0; j < MAN_SEG; ++j) {
            float4 xc = __ldg(rp + j * MAN_DV);
            float4 va = __ldg(rp + (j + MAN_H) * MAN_DV);
            float4 vr = __ldg(rp + (j - MAN_H) * MAN_DV);
            float4 r;
            r.x = norm1(xc.x, s1.x, s2.x, inv_k, inv_k1);
            r.y = norm1(xc.y, s1.y, s2.y, inv_k, inv_k1);
            r.z = norm1(xc.z, s1.z, s2.z, inv_k, inv_k1);
            r.w = norm1(xc.w, s1.w, s2.w, inv_k, inv_k1);
            __stcs(ob + j * MAN_DV, r);
            step(s1, s2, va, vr);
        }
    } else {
        const int tg = t0 + ts;
        float4 lo1 = g1[(2 * seg) * MAN_DV + dv];
        float4 hi1 = g1[(2 * seg + 12) * MAN_DV + dv];
        float4 lo2 = g2[(2 * seg) * MAN_DV + dv];
        float4 hi2 = g2[(2 * seg + 12) * MAN_DV + dv];
        float4 s1 = make_float4(hi1.x - lo1.x, hi1.y - lo1.y,
                                hi1.z - lo1.z, hi1.w - lo1.w);
        float4 s2 = make_float4(hi2.x - lo2.x, hi2.y - lo2.y,
                                hi2.z - lo2.z, hi2.w - lo2.w);
        #pragma unroll 1
        for (int i = 0; i < 4; ++i)
            acc(s1, s2, __ldg(xb + refl(tg + 46 + i) * MAN_DV + dv));
        #pragma unroll 1
        for (int j = 0; j < MAN_SEG; ++j) {
            float4 xc = __ldg(xb + (tg + j) * MAN_DV + dv);
            float4 va = __ldg(xb + refl(tg + j + MAN_H) * MAN_DV + dv);
            float4 vr = __ldg(xb + refl(tg + j - MAN_H) * MAN_DV + dv);
            float4 r;
            r.x = norm1(xc.x, s1.x, s2.x, inv_k, inv_k1);
            r.y = norm1(xc.y, s1.y, s2.y, inv_k, inv_k1);
            r.z = norm1(xc.z, s1.z, s2.z, inv_k, inv_k1);
            r.w = norm1(xc.w, s1.w, s2.w, inv_k, inv_k1);
            __stcs(ob + j * MAN_DV, r);
            step(s1, s2, va, vr);
        }
    }
}

extern "C" void kernel_launch(void* const* d_in, const int* in_sizes, int n_in,
                              void* d_out, int out_size)
{
    const float4* x = (const float4*)d_in[0];
    float4* out = (float4*)d_out;
    (void)in_sizes; (void)n_in; (void)out_size;

    static bool attr_done = false;
    if (!attr_done) {
        cudaFuncSetAttribute(moving_avg_norm_v12,
                             cudaFuncAttributePreferredSharedMemoryCarveout, 50);
        attr_done = true;
    }

    const int grid = MAN_B * MAN_NCHUNK;   // 2048 blocks
    moving_avg_norm_v12<<<grid, MAN_NTH, MAN_SMEM>>>(x, out);
}

// round 13
// speedup vs baseline: 1.0708x; 1.0708x over previous
#include <cuda_runtime.h>

// MovingAvgNorm: x (B=32, T=16384, D=80) fp32, window K=100 over T,
// reflect pad (50 left, 49 right), unbiased std.
//
// R13: R11 champion config (TSUB=256, NTH=320, tid-strided 8-row group sums,
// prefix init, 48-reg / 4-block regime, carveout hint) with two serialization
// cuts: (a) scan combines group PAIRS (21 serial iters instead of 43; phase 3
// only reads even prefix indices), (b) the 4 remainder LDGs issue BEFORE the
// scan barrier so their global latency hides under the scan.

#define MAN_B      32
#define MAN_T      16384
#define MAN_DV     20          // 80 floats = 20 float4
#define MAN_K      100
#define MAN_H      50
#define MAN_TSUB   256
#define MAN_NTH    320
#define MAN_SEG    16
#define MAN_NCHUNK (MAN_T / MAN_TSUB)     // 64
#define MAN_G      8
#define MAN_NGRP   42                      // groups cover local rows 0..335
#define MAN_GPRE   (MAN_NGRP + 1)          // 43 (prefix slots, even used)
#define MAN_GARR   (MAN_GPRE * MAN_DV)     // 860 float4 per array
#define MAN_SMEM   (2 * MAN_GARR * 16)     // 27520 B

__device__ __forceinline__ int refl(int o) {
    if (o < 0) return -o;
    if (o >= MAN_T) return 2 * MAN_T - 2 - o;
    return o;
}

__device__ __forceinline__ void acc(float4& s1, float4& s2, float4 v) {
    s1.x += v.x; s1.y += v.y; s1.z += v.z; s1.w += v.w;
    s2.x = fmaf(v.x, v.x, s2.x);
    s2.y = fmaf(v.y, v.y, s2.y);
    s2.z = fmaf(v.z, v.z, s2.z);
    s2.w = fmaf(v.w, v.w, s2.w);
}

__device__ __forceinline__ float norm1(float xc, float s1, float s2,
                                       float inv_k, float inv_k1) {
    float m   = s1 * inv_k;
    float var = (s2 - s1 * m) * inv_k1;
    float rsd = rsqrtf(fmaxf(var, 1e-24f));
    return (xc - m) * rsd;
}

__device__ __forceinline__ void step(float4& s1, float4& s2,
                                     float4 va, float4 vr) {
    s1.x += va.x - vr.x;  s1.y += va.y - vr.y;
    s1.z += va.z - vr.z;  s1.w += va.w - vr.w;
    s2.x = fmaf(va.x, va.x, fmaf(-vr.x, vr.x, s2.x));
    s2.y = fmaf(va.y, va.y, fmaf(-vr.y, vr.y, s2.y));
    s2.z = fmaf(va.z, va.z, fmaf(-vr.z, vr.z, s2.z));
    s2.w = fmaf(va.w, va.w, fmaf(-vr.w, vr.w, s2.w));
}

__global__ __launch_bounds__(MAN_NTH, 4) void moving_avg_norm_v13(
    const float4* __restrict__ x, float4* __restrict__ out)
{
    extern __shared__ float4 smem[];
    float4* g1 = smem;              // [43*20] group sums -> even-slot prefix
    float4* g2 = smem + MAN_GARR;   // [43*20]

    const int b  = blockIdx.x / MAN_NCHUNK;
    const int c  = blockIdx.x % MAN_NCHUNK;
    const int t0 = c * MAN_TSUB;

    const float4* __restrict__ xb = x + (size_t)b * MAN_T * MAN_DV;
    const bool edge = (c == 0) || (c == MAN_NCHUNK - 1);

    // phase-3 thread mapping (computed early; q loads issued before the scan)
    const int dv  = threadIdx.x % MAN_DV;
    const int seg = threadIdx.x / MAN_DV;      // 0..15
    const int ts  = seg * MAN_SEG;             // local output row start
    const float4* rp = xb + (t0 + ts) * MAN_DV + dv;

    // ---- phase 1: 8-row group sums, tid-strided (R11-verified layout) ----
    if (!edge) {
        #pragma unroll 3
        for (int idx = threadIdx.x; idx < MAN_NGRP * MAN_DV; idx += MAN_NTH) {
            const int g   = idx / MAN_DV;
            const int dvv = idx % MAN_DV;
            const float4* gp = xb + (t0 - MAN_H + g * MAN_G) * MAN_DV + dvv;
            float4 v0 = __ldg(gp + 0 * MAN_DV);
            float4 v1 = __ldg(gp + 1 * MAN_DV);
            float4 v2 = __ldg(gp + 2 * MAN_DV);
            float4 v3 = __ldg(gp + 3 * MAN_DV);
            float4 v4 = __ldg(gp + 4 * MAN_DV);
            float4 v5 = __ldg(gp + 5 * MAN_DV);
            float4 v6 = __ldg(gp + 6 * MAN_DV);
            float4 v7 = __ldg(gp + 7 * MAN_DV);
            float4 p1 = make_float4(0.f, 0.f, 0.f, 0.f);
            float4 p2 = make_float4(0.f, 0.f, 0.f, 0.f);
            acc(p1, p2, v0); acc(p1, p2, v1); acc(p1, p2, v2); acc(p1, p2, v3);
            acc(p1, p2, v4); acc(p1, p2, v5); acc(p1, p2, v6); acc(p1, p2, v7);
            g1[idx] = p1;
            g2[idx] = p2;
        }
    } else {
        #pragma unroll 1
        for (int idx = threadIdx.x; idx < MAN_NGRP * MAN_DV; idx += MAN_NTH) {
            const int g   = idx / MAN_DV;
            const int dvv = idx % MAN_DV;
            const int r0  = t0 - MAN_H + g * MAN_G;
            float4 p1 = make_float4(0.f, 0.f, 0.f, 0.f);
            float4 p2 = make_float4(0.f, 0.f, 0.f, 0.f);
            #pragma unroll 1
            for (int i = 0; i < MAN_G; ++i)
                acc(p1, p2, __ldg(xb + refl(r0 + i) * MAN_DV + dvv));
            g1[idx] = p1;
            g2[idx] = p2;
        }
    }
    __syncthreads();

    // ---- hoisted remainder loads (rows ts+96..99): independent of the scan,
    //      issued now so their latency hides under phase 2 ----
    float4 q0, q1, q2, q3;
    if (!edge) {
        q0 = __ldg(rp + 46 * MAN_DV);
        q1 = __ldg(rp + 47 * MAN_DV);
        q2 = __ldg(rp + 48 * MAN_DV);
        q3 = __ldg(rp + 49 * MAN_DV);
    } else {
        const int tg = t0 + ts;
        q0 = __ldg(xb + refl(tg + 46) * MAN_DV + dv);
        q1 = __ldg(xb + refl(tg + 47) * MAN_DV + dv);
        q2 = __ldg(xb + refl(tg + 48) * MAN_DV + dv);
        q3 = __ldg(xb + refl(tg + 49) * MAN_DV + dv);
    }

    // ---- phase 2: pairwise exclusive prefix over groups, EVEN slots only
    //      (phase 3 reads indices 2s and 2s+12 exclusively). 21 serial iters.
    //      In-place safe: g[2p] read before overwrite; odd slots untouched. ----
    if (threadIdx.x < 2 * MAN_DV) {
        float4* A = (threadIdx.x < MAN_DV) ? g1 : g2;
        const int dvv = threadIdx.x % MAN_DV;
        float4 run = make_float4(0.f, 0.f, 0.f, 0.f);
        #pragma unroll 7
        for (int p = 0; p < MAN_NGRP / 2; ++p) {
            float4 a = A[(2 * p) * MAN_DV + dvv];
            float4 bb = A[(2 * p + 1) * MAN_DV + dvv];
            A[(2 * p) * MAN_DV + dvv] = run;
            run.x += a.x + bb.x; run.y += a.y + bb.y;
            run.z += a.z + bb.z; run.w += a.w + bb.w;
        }
        A[MAN_NGRP * MAN_DV + dvv] = run;   // slot 42 (even)
    }
    __syncthreads();

    // ---- phase 3: 20 dv-lanes x 16 segments of 16 outputs ----
    const float inv_k  = 1.0f / MAN_K;
    const float inv_k1 = 1.0f / (MAN_K - 1);

    // window [ts, ts+100) = groups 2s..2s+11 (96 rows) + rows ts+96..99
    float4 lo1 = g1[(2 * seg) * MAN_DV + dv];
    float4 hi1 = g1[(2 * seg + 12) * MAN_DV + dv];
    float4 lo2 = g2[(2 * seg) * MAN_DV + dv];
    float4 hi2 = g2[(2 * seg + 12) * MAN_DV + dv];
    float4 s1 = make_float4(hi1.x - lo1.x, hi1.y - lo1.y,
                            hi1.z - lo1.z, hi1.w - lo1.w);
    float4 s2 = make_float4(hi2.x - lo2.x, hi2.y - lo2.y,
                            hi2.z - lo2.z, hi2.w - lo2.w);
    acc(s1, s2, q0); acc(s1, s2, q1); acc(s1, s2, q2); acc(s1, s2, q3);

    float4* __restrict__ ob = out + ((size_t)b * MAN_T + t0 + ts) * MAN_DV + dv;

    if (!edge) {
        #pragma unroll 8
        for (int j = 0; j < MAN_SEG; ++j) {
            float4 xc = __ldg(rp + j * MAN_DV);
            float4 va = __ldg(rp + (j + MAN_H) * MAN_DV);
            float4 vr = __ldg(rp + (j - MAN_H) * MAN_DV);
            float4 r;
            r.x = norm1(xc.x, s1.x, s2.x, inv_k, inv_k1);
            r.y = norm1(xc.y, s1.y, s2.y, inv_k, inv_k1);
            r.z = norm1(xc.z, s1.z, s2.z, inv_k, inv_k1);
            r.w = norm1(xc.w, s1.w, s2.w, inv_k, inv_k1);
            __stcs(ob + j * MAN_DV, r);
            step(s1, s2, va, vr);
        }
    } else {
        const int tg = t0 + ts;
        #pragma unroll 1
        for (int j = 0; j < MAN_SEG; ++j) {
            float4 xc = __ldg(xb + (tg + j) * MAN_DV + dv);
            float4 va = __ldg(xb + refl(tg + j + MAN_H) * MAN_DV + dv);
            float4 vr = __ldg(xb + refl(tg + j - MAN_H) * MAN_DV + dv);
            float4 r;
            r.x = norm1(xc.x, s1.x, s2.x, inv_k, inv_k1);
            r.y = norm1(xc.y, s1.y, s2.y, inv_k, inv_k1);
            r.z = norm1(xc.z, s1.z, s2.z, inv_k, inv_k1);
            r.w = norm1(xc.w, s1.w, s2.w, inv_k, inv_k1);
            __stcs(ob + j * MAN_DV, r);
            step(s1, s2, va, vr);
        }
    }
}

extern "C" void kernel_launch(void* const* d_in, const int* in_sizes, int n_in,
                              void* d_out, int out_size)
{
    const float4* x = (const float4*)d_in[0];
    float4* out = (float4*)d_out;
    (void)in_sizes; (void)n_in; (void)out_size;

    static bool attr_done = false;
    if (!attr_done) {
        cudaFuncSetAttribute(moving_avg_norm_v13,
                             cudaFuncAttributePreferredSharedMemoryCarveout, 50);
        attr_done = true;
    }

    const int grid = MAN_B * MAN_NCHUNK;   // 2048 blocks
    moving_avg_norm_v13<<<grid, MAN_NTH, MAN_SMEM>>>(x, out);
}